// round 12
// baseline (speedup 1.0000x reference)
#include <cuda_runtime.h>
#include <cuda_bf16.h>

#define LSEQ 2048
#define NH 128
#define NSTATE 128

// Scratch for synthesized conv kernels Kl[h][l] (1 MB, static device global -> allowed)
__device__ float g_Kl[NH * LSEQ];

// ---------------------------------------------------------------------------
// Kernel 1: Kl[h,l] = dot(C[h,:], K[l,h,:]).  TWO rows per warp. (unchanged;
// measured ~22us, ~6.1 TB/s HBM)
// ---------------------------------------------------------------------------
__global__ __launch_bounds__(256) void kl_kernel(const float* __restrict__ K,
                                                 const float* __restrict__ C) {
    int gw   = (blockIdx.x * 256 + threadIdx.x) >> 5;
    int lane = threadIdx.x & 31;
    int r0   = gw * 2;
    int h0   = r0 & (NH - 1);
    int l    = r0 >> 7;

    const float4* krow = reinterpret_cast<const float4*>(K) + (size_t)r0 * 32;
    const float4* crow = reinterpret_cast<const float4*>(C) + (size_t)h0 * 32;
    float4 kv0 = krow[lane];
    float4 kv1 = krow[32 + lane];
    float4 cv0 = crow[lane];
    float4 cv1 = crow[32 + lane];
    float p0 = kv0.x * cv0.x + kv0.y * cv0.y + kv0.z * cv0.z + kv0.w * cv0.w;
    float p1 = kv1.x * cv1.x + kv1.y * cv1.y + kv1.z * cv1.z + kv1.w * cv1.w;

#pragma unroll
    for (int off = 16; off > 0; off >>= 1) {
        p0 += __shfl_xor_sync(0xffffffffu, p0, off);
        p1 += __shfl_xor_sync(0xffffffffu, p1, off);
    }

    if (lane == 0) {
        g_Kl[h0 * LSEQ + l]       = p0;
        g_Kl[(h0 + 1) * LSEQ + l] = p1;
    }
}

// ---------------------------------------------------------------------------
// Kernel 2: depthwise 'same' conv + skip, packed f32x2 version.
//   y[h,i] = sum_j Kl[h,j] * u[h, i+1023-j]  +  D[h]*u[h,i]
// Each thread computes 8 outputs as 4 f32x2 accumulator pairs. The 16-slot
// sliding window is held as 8 aligned pairs wp[m]=(w[2m],w[2m+1]) for even
// taps and 8 shifted pairs ws[m]=(w[2m+1],w[2m+2 mod16]) for odd taps.
// k broadcast pairs (k,k) come from a duplicated smem array via one LDS.64.
// FFMA2 count/iter = 64 (vs 128 FFMA scalar) -> fma-pipe floor halves.
// ---------------------------------------------------------------------------
#define USZ  3328   // max padded-u index touched is 3327
#define KSZ  2064   // 2048 + 16 zero pad
#define UOFF 1025   // padded index = u index + 1025

#define PACK2(dst, lo, hi) \
    asm("mov.b64 %0, {%1, %2};" : "=l"(dst) : "f"(lo), "f"(hi))
#define UNPACK2(lo, hi, src) \
    asm("mov.b64 {%0, %1}, %2;" : "=f"(lo), "=f"(hi) : "l"(src))
#define FMA2(acc, a, b) \
    asm("fma.rn.f32x2 %0, %1, %2, %0;" : "+l"(acc) : "l"(a), "l"(b))

__global__ __launch_bounds__(256) void conv_kernel(const float* __restrict__ u,
                                                   const float* __restrict__ D,
                                                   float* __restrict__ y) {
    __shared__ __align__(16) float s_u[USZ];
    __shared__ __align__(16) float s_k2[2 * KSZ];   // duplicated: (k[j], k[j])

    int h   = blockIdx.x;
    int tid = threadIdx.x;

    const float* urow = u + h * LSEQ;
    for (int p = tid; p < USZ; p += 256) {
        int q = p - UOFF;
        s_u[p] = (q >= 0 && q < LSEQ) ? urow[q] : 0.0f;
    }
    const float* krow = g_Kl + h * LSEQ;
    for (int p = tid; p < KSZ; p += 256) {
        float kv = (p < LSEQ) ? krow[p] : 0.0f;
        s_k2[2 * p]     = kv;
        s_k2[2 * p + 1] = kv;
    }
    __syncthreads();

    int warp  = tid >> 5;
    int i0    = tid * 8;           // outputs i0 .. i0+7
    int wbase = warp * 256;
    int jlo = (wbase > 1024) ? (wbase - 1024) : 0;        // multiple of 16
    int jhi = wbase + 1278; if (jhi > 2047) jhi = 2047;
    int cnt = (jhi - jlo + 1 + 15) & ~15;                 // padded taps are 0

    unsigned long long acc2[4] = {0ull, 0ull, 0ull, 0ull};  // (+0,+0) pairs
    unsigned long long wp[8], ws[8];

    int b0 = i0 + 2048 - jlo;      // padded-u base at j = jlo (mult of 8)
    float m0;                       // carry: scalar u[b] (slot 0)
    {
        float4 a = *reinterpret_cast<const float4*>(&s_u[b0]);
        float4 c = *reinterpret_cast<const float4*>(&s_u[b0 + 4]);
        PACK2(wp[0], a.x, a.y); PACK2(wp[1], a.z, a.w);
        PACK2(wp[2], c.x, c.y); PACK2(wp[3], c.z, c.w);
        PACK2(ws[0], a.y, a.z); PACK2(ws[1], a.w, c.x);
        PACK2(ws[2], c.y, c.z);
        // ws[3..7], wp[4..7] written inside the loop before any use
        m0 = a.x;
    }

    const unsigned long long* k2 = reinterpret_cast<const unsigned long long*>(s_k2);

    int j = jlo;
    int b = b0;
    for (int it = 0; it < cnt; it += 16) {
        // ---- phase A refill: slots 8..15 <- u[b-8 .. b-1] ----
        float4 na = *reinterpret_cast<const float4*>(&s_u[b - 8]);
        float4 nb = *reinterpret_cast<const float4*>(&s_u[b - 4]);
        PACK2(wp[4], na.x, na.y); PACK2(wp[5], na.z, na.w);
        PACK2(wp[6], nb.x, nb.y); PACK2(wp[7], nb.z, nb.w);
        PACK2(ws[4], na.y, na.z); PACK2(ws[5], na.w, nb.x);
        PACK2(ws[6], nb.y, nb.z); PACK2(ws[7], nb.w, m0);   // (w15, w0)

        // ---- taps p = 0..7 ----
#pragma unroll
        for (int p = 0; p < 8; ++p) {
            unsigned long long kv = k2[j + p];   // warp-uniform LDS.64 (k,k)
            if ((p & 1) == 0) {
#pragma unroll
                for (int q = 0; q < 4; ++q)
                    FMA2(acc2[q], kv, wp[(q - p / 2) & 7]);
            } else {
#pragma unroll
                for (int q = 0; q < 4; ++q)
                    FMA2(acc2[q], kv, ws[(q - (p + 1) / 2) & 7]);
            }
        }

        // ---- phase B refill: slots 0..7 <- u[b-16 .. b-9] ----
        float4 ma = *reinterpret_cast<const float4*>(&s_u[b - 16]);
        float4 mb = *reinterpret_cast<const float4*>(&s_u[b - 12]);
        PACK2(wp[0], ma.x, ma.y); PACK2(wp[1], ma.z, ma.w);
        PACK2(wp[2], mb.x, mb.y); PACK2(wp[3], mb.z, mb.w);
        PACK2(ws[0], ma.y, ma.z); PACK2(ws[1], ma.w, mb.x);
        PACK2(ws[2], mb.y, mb.z); PACK2(ws[3], mb.w, na.x); // (w7, w8)

        // ---- taps p = 8..15 ----
#pragma unroll
        for (int p = 8; p < 16; ++p) {
            unsigned long long kv = k2[j + p];
            if ((p & 1) == 0) {
#pragma unroll
                for (int q = 0; q < 4; ++q)
                    FMA2(acc2[q], kv, wp[(q - p / 2) & 7]);
            } else {
#pragma unroll
                for (int q = 0; q < 4; ++q)
                    FMA2(acc2[q], kv, ws[(q - (p + 1) / 2) & 7]);
            }
        }

        m0 = ma.x;      // new u[b-16] becomes next iter's slot-0 scalar
        j += 16;
        b -= 16;
    }

    float d = D[h];
    float out[8];
#pragma unroll
    for (int q = 0; q < 4; ++q) {
        float lo, hi;
        UNPACK2(lo, hi, acc2[q]);
        out[2 * q]     = lo + d * s_u[UOFF + i0 + 2 * q];
        out[2 * q + 1] = hi + d * s_u[UOFF + i0 + 2 * q + 1];
    }

    float4* yrow = reinterpret_cast<float4*>(y + h * LSEQ + i0);
    float4 o0 = {out[0], out[1], out[2], out[3]};
    float4 o1 = {out[4], out[5], out[6], out[7]};
    yrow[0] = o0;
    yrow[1] = o1;
}

// ---------------------------------------------------------------------------
// kernel_launch: map inputs by element count (all four sizes are distinct).
// ---------------------------------------------------------------------------
extern "C" void kernel_launch(void* const* d_in, const int* in_sizes, int n_in,
                              void* d_out, int out_size) {
    const float* u = nullptr;
    const float* C = nullptr;
    const float* D = nullptr;
    const float* K = nullptr;
    for (int i = 0; i < n_in; ++i) {
        switch (in_sizes[i]) {
            case NH * LSEQ:          u = (const float*)d_in[i]; break;   // 262144
            case NH * NSTATE:        C = (const float*)d_in[i]; break;   // 16384
            case NH:                 D = (const float*)d_in[i]; break;   // 128
            default:
                if (in_sizes[i] == LSEQ * NH * NSTATE)                   // 33554432
                    K = (const float*)d_in[i];
                break;
        }
    }

    kl_kernel<<<(LSEQ * NH) / 16, 256>>>(K, C);
    conv_kernel<<<NH, 256>>>(u, D, (float*)d_out);
}

// round 13
// speedup vs baseline: 1.2087x; 1.2087x over previous
#include <cuda_runtime.h>
#include <cuda_bf16.h>

#define LSEQ 2048
#define NH 128
#define NSTATE 128

#define USZ  3328   // padded u; max index touched is 3327
#define UOFF 1025   // padded index = u index + 1025

// Production order: interleave high/low chunks so late-range warps (w5-w7)
// get ready work early while early-range warps (w0-w2) are also served.
__constant__ int c_P[16] = {6, 7, 0, 8, 1, 9, 2, 10, 3, 11, 4, 12, 5, 13, 14, 15};

// ---------------------------------------------------------------------------
// Fused kernel: one block per channel h.
//  Phase structure (16 rounds):
//   round r: dot chunk P[r] (K rows preloaded into regs last round) -> s_k
//            __syncthreads
//            issue LDGs for chunk P[r+1] (latency hidden under conv)
//            run conv budget B_w iters from ready chunks (cursor over P order)
//  drain: finish remaining conv iters (all chunks ready).
// Conv body = R11 scalar 16-slot register sliding window (proven 30.5us).
// ---------------------------------------------------------------------------
__global__ __launch_bounds__(256) void fused_kernel(const float* __restrict__ K,
                                                    const float* __restrict__ C,
                                                    const float* __restrict__ u,
                                                    const float* __restrict__ D,
                                                    float* __restrict__ y) {
    __shared__ __align__(16) float s_u[USZ];
    __shared__ __align__(16) float s_k[LSEQ];

    int h    = blockIdx.x;
    int tid  = threadIdx.x;
    int warp = tid >> 5;
    int lane = tid & 31;

    // ---- load u (zero-padded) ----
    const float* urow = u + h * LSEQ;
    for (int p = tid; p < USZ; p += 256) {
        int q = p - UOFF;
        s_u[p] = (q >= 0 && q < LSEQ) ? urow[q] : 0.0f;
    }

    // ---- per-lane C slice (reused for every dot) ----
    float4 cv = reinterpret_cast<const float4*>(C + h * NSTATE)[lane];

    // ---- per-warp conv chunk range (all chunk-aligned; audited) ----
    int clo = (warp <= 4) ? 0 : 2 * (warp - 4);                 // {0,0,0,0,0,2,4,6}
    int n_w = (warp <= 3) ? (10 + 2 * warp)
                          : ((warp == 4) ? 16 : 10 + 2 * (7 - warp)); // {10,12,14,16,16,14,12,10}
    int chi = clo + n_w;
    int B   = n_w >> 1;                                         // {5,6,7,8,8,7,6,5}

    int i0 = tid * 8;   // this thread's outputs i0..i0+7

    float acc[8];
#pragma unroll
    for (int r = 0; r < 8; ++r) acc[r] = 0.0f;

    const float4* Kbase = reinterpret_cast<const float4*>(K);

    // ---- prologue: issue LDGs for chunk P[0] (rows 16w..16w+15 of chunk) ----
    float4 kreg[16];
    {
        int c = c_P[0];
#pragma unroll
        for (int m = 0; m < 16; ++m) {
            int l = 128 * c + 16 * warp + m;
            kreg[m] = Kbase[(size_t)(l * NH + h) * 32 + lane];
        }
    }
    __syncthreads();    // s_u ready before any conv

    int pos = 0, sub = 0;   // cursor into P order (warp-filtered), sub-iter 0..7

    // conv_run: n sequential 16-tap iterations starting at (chunk c, sub s).
    auto conv_run = [&](int c, int s, int n) {
        int j = 128 * c + 16 * s;
        int b = i0 + 2048 - j;           // padded-u base (b = i0 mod 16)
        float w[16];
        {
            float4 a = *reinterpret_cast<const float4*>(&s_u[b]);
            float4 cc = *reinterpret_cast<const float4*>(&s_u[b + 4]);
            w[0] = a.x; w[1] = a.y; w[2] = a.z; w[3] = a.w;
            w[4] = cc.x; w[5] = cc.y; w[6] = cc.z; w[7] = cc.w;
        }
        for (int it = 0; it < n; ++it) {
            float4 ka = *reinterpret_cast<const float4*>(&s_k[j]);
            float4 kb = *reinterpret_cast<const float4*>(&s_k[j + 4]);
            float4 kc = *reinterpret_cast<const float4*>(&s_k[j + 8]);
            float4 kd = *reinterpret_cast<const float4*>(&s_k[j + 12]);
            float kk[16] = {ka.x, ka.y, ka.z, ka.w, kb.x, kb.y, kb.z, kb.w,
                            kc.x, kc.y, kc.z, kc.w, kd.x, kd.y, kd.z, kd.w};
            {   // refill slots 8..15 <- s_u[b-8 .. b-1]
                float4 a = *reinterpret_cast<const float4*>(&s_u[b - 8]);
                float4 cc = *reinterpret_cast<const float4*>(&s_u[b - 4]);
                w[8]  = a.x; w[9]  = a.y; w[10] = a.z; w[11] = a.w;
                w[12] = cc.x; w[13] = cc.y; w[14] = cc.z; w[15] = cc.w;
            }
#pragma unroll
            for (int p = 0; p < 8; ++p) {
                float kv = kk[p];
#pragma unroll
                for (int r = 0; r < 8; ++r)
                    acc[r] += kv * w[(r - p) & 15];
            }
            {   // refill slots 0..7 <- s_u[b-16 .. b-9]
                float4 a = *reinterpret_cast<const float4*>(&s_u[b - 16]);
                float4 cc = *reinterpret_cast<const float4*>(&s_u[b - 12]);
                w[0] = a.x; w[1] = a.y; w[2] = a.z; w[3] = a.w;
                w[4] = cc.x; w[5] = cc.y; w[6] = cc.z; w[7] = cc.w;
            }
#pragma unroll
            for (int p = 8; p < 16; ++p) {
                float kv = kk[p];
#pragma unroll
                for (int r = 0; r < 8; ++r)
                    acc[r] += kv * w[(r - p) & 15];
            }
            j += 16;
            b -= 16;
        }
    };

    // ---- 16 production rounds ----
    for (int r = 0; r < 16; ++r) {
        // (1) dot chunk P[r] from kreg (loaded last round), store to s_k
        {
            int c = c_P[r];
            float myk = 0.0f;
#pragma unroll
            for (int m = 0; m < 16; ++m) {
                float4 kv = kreg[m];
                float p = kv.x * cv.x + kv.y * cv.y + kv.z * cv.z + kv.w * cv.w;
#pragma unroll
                for (int off = 16; off > 0; off >>= 1)
                    p += __shfl_xor_sync(0xffffffffu, p, off);
                if (lane == m) myk = p;     // lane m keeps row m's value
            }
            if (lane < 16) s_k[128 * c + 16 * warp + lane] = myk;
        }
        __syncthreads();   // chunk P[r] visible block-wide

        // (2) issue LDGs for next chunk (hidden under conv below)
        if (r < 15) {
            int c = c_P[r + 1];
#pragma unroll
            for (int m = 0; m < 16; ++m) {
                int l = 128 * c + 16 * warp + m;
                kreg[m] = Kbase[(size_t)(l * NH + h) * 32 + lane];
            }
        }

        // (3) conv: up to B iters from ready chunks (P-position <= r)
        int budget = B;
        while (budget > 0 && pos < 16) {
            int c = c_P[pos];
            if (c < clo || c >= chi) { pos++; sub = 0; continue; }   // not ours
            if (pos > r) break;                                      // not ready
            int take = (budget < 8 - sub) ? budget : (8 - sub);
            conv_run(c, sub, take);
            sub += take;
            budget -= take;
            if (sub == 8) { pos++; sub = 0; }
        }
    }

    // ---- drain: everything is ready now ----
    while (pos < 16) {
        int c = c_P[pos];
        if (c >= clo && c < chi) conv_run(c, sub, 8 - sub);
        pos++; sub = 0;
    }

    // ---- epilogue: skip connection + store ----
    float d = D[h];
    float out[8];
#pragma unroll
    for (int r = 0; r < 8; ++r)
        out[r] = acc[r] + d * s_u[UOFF + i0 + r];

    float4* yrow = reinterpret_cast<float4*>(y + h * LSEQ + i0);
    float4 o0 = {out[0], out[1], out[2], out[3]};
    float4 o1 = {out[4], out[5], out[6], out[7]};
    yrow[0] = o0;
    yrow[1] = o1;
}

// ---------------------------------------------------------------------------
// kernel_launch: map inputs by element count (all four sizes are distinct).
//   u:262144  C:16384  D:128  K_mats:33554432   -> y:262144 (float32)
// ---------------------------------------------------------------------------
extern "C" void kernel_launch(void* const* d_in, const int* in_sizes, int n_in,
                              void* d_out, int out_size) {
    const float* u = nullptr;
    const float* C = nullptr;
    const float* D = nullptr;
    const float* K = nullptr;
    for (int i = 0; i < n_in; ++i) {
        switch (in_sizes[i]) {
            case NH * LSEQ:          u = (const float*)d_in[i]; break;   // 262144
            case NH * NSTATE:        C = (const float*)d_in[i]; break;   // 16384
            case NH:                 D = (const float*)d_in[i]; break;   // 128
            default:
                if (in_sizes[i] == LSEQ * NH * NSTATE)                   // 33554432
                    K = (const float*)d_in[i];
                break;
        }
    }

    fused_kernel<<<NH, 256>>>(K, C, u, D, (float*)d_out);
}